// round 11
// baseline (speedup 1.0000x reference)
#include <cuda_runtime.h>
#include <cuda_bf16.h>
#include <cstdint>

// LogitSeparator: out[b,d,j] = logits[b, start(b,d)+j] for j < len(b,d) else 0
//                 mask[b,d,j] = (j < len) ? 1.0 : 0.0
// start = exclusive cumsum of schemas[b,:] at d; len = schemas[b,d] in [0,256).
// Output layout: [out (B*D*L f32)] ++ [mask (B*D*L f32)]  (verified, rel_err 0).
//
// R11: dual-engine concurrent fill. Measured rates: SM stores ~6.5 TB/s,
// pitched CE memset2D ~5.6 TB/s, HBM write wall ~7+. Split the 134MB so both
// engines run flat out in parallel on disjoint regions:
//   SM kernel : values half (strip gather + bulk zeros, 64MB) + mask strip (2MB)
//   CE branch : mask-half bulk, cols [256,L) x n_rows (62MB) via memset2D
// Fork/join graph branches (proven in R10). Deterministic; no allocation.

#define D_DIM 32
#define STRIP 256            // live columns: len <= 255 < STRIP

__global__ void __launch_bounds__(512)
values_plus_maskstrip_kernel(const unsigned int* __restrict__ schemas_w,
                             const float* __restrict__ logits,
                             float* __restrict__ out,
                             int n_rows, int L) {
    const int row = blockIdx.x;               // b*D + d
    const int b   = row >> 5;                 // D_DIM == 32
    const int d   = row & (D_DIM - 1);
    const int tid = threadIdx.x;

    // ---- meta (warps 0-1 only, warp-redundant, no smem/barrier) ----
    int start = 0, len = 0;
    if (tid < 64) {
        const int lane = tid & 31;
        const int idx  = (b << 5) + lane;
        // dtype detect: int64 schemas in [0,256) -> odd 32-bit words all zero
        unsigned int oddw = schemas_w[2 * lane + 1];
        unsigned int v32  = schemas_w[idx];
        bool is64 = (__ballot_sync(0xffffffffu, oddw != 0u) == 0u);
        int v = (int)(is64 ? schemas_w[2 * idx] : v32);

        int x = v;
        #pragma unroll
        for (int o = 1; o < 32; o <<= 1) {
            int y = __shfl_up_sync(0xffffffffu, x, o);
            if (lane >= o) x += y;
        }
        start = __shfl_sync(0xffffffffu, x - v, d);
        len   = __shfl_sync(0xffffffffu, v, d);
    }

    float4* __restrict__ vrow =
        reinterpret_cast<float4*>(out + (long long)row * L);
    const float4 z4 = make_float4(0.f, 0.f, 0.f, 0.f);

    // ---- values row, iteration 0: vectors 0..511 (only tid<64 live) ----
    float4 w = z4;
    if (tid < 64) {
        const int j = tid << 2;
        const float* __restrict__ lrow = logits + (long long)b * L + start;
        if (j + 3 < len) {
            w.x = lrow[j + 0];
            w.y = lrow[j + 1];
            w.z = lrow[j + 2];
            w.w = lrow[j + 3];
        } else if (j < len) {
            if (j + 0 < len) w.x = lrow[j + 0];
            if (j + 1 < len) w.y = lrow[j + 1];
            if (j + 2 < len) w.z = lrow[j + 2];
        }
    }
    vrow[tid] = w;

    // ---- mask strip: columns [0, STRIP) of the mask half ----
    if (tid < 64) {
        const int j = tid << 2;
        float4 mk = z4;
        if (j + 0 < len) mk.x = 1.f;
        if (j + 1 < len) mk.y = 1.f;
        if (j + 2 < len) mk.z = 1.f;
        if (j + 3 < len) mk.w = 1.f;
        *reinterpret_cast<float4*>(
            out + (long long)n_rows * L + (long long)row * L + j) = mk;
    }

    // ---- values row, iterations 1..3: branch-free zero streaming ----
    const int nvec = L >> 2;                  // 2048
    #pragma unroll 4
    for (int v = tid + 512; v < nvec; v += 512)
        vrow[v] = z4;
}

static cudaStream_t g_side = nullptr;
static cudaEvent_t  g_fork = nullptr;
static cudaEvent_t  g_join = nullptr;

extern "C" void kernel_launch(void* const* d_in, const int* in_sizes, int n_in,
                              void* d_out, int out_size) {
    const unsigned int* schemas_w = (const unsigned int*)d_in[0];
    const float*        logits    = (const float*)d_in[1];
    float*              out       = (float*)d_out;

    int n_rows = in_sizes[0];             // B*D = 2048
    int B      = n_rows / D_DIM;          // 64
    int L      = in_sizes[1] / B;         // 8192

    if (g_side == nullptr) {
        cudaStreamCreateWithFlags(&g_side, cudaStreamNonBlocking);
        cudaEventCreateWithFlags(&g_fork, cudaEventDisableTiming);
        cudaEventCreateWithFlags(&g_join, cudaEventDisableTiming);
    }

    // Fork side stream into the captured graph.
    cudaEventRecord(g_fork, 0);
    cudaStreamWaitEvent(g_side, g_fork, 0);

    // Branch A (CE): zero mask-half bulk, cols [STRIP, L) of n_rows rows.
    cudaMemset2DAsync(out + (long long)n_rows * L + STRIP,
                      (size_t)L * sizeof(float),            // pitch
                      0,
                      (size_t)(L - STRIP) * sizeof(float),  // width
                      (size_t)n_rows,                       // height
                      g_side);

    // Branch B (SM): values half (strip + bulk zeros) + mask strip.
    values_plus_maskstrip_kernel<<<n_rows, 512>>>(schemas_w, logits, out,
                                                  n_rows, L);

    // Join.
    cudaEventRecord(g_join, g_side);
    cudaStreamWaitEvent(0, g_join, 0);
}

// round 13
// speedup vs baseline: 1.0039x; 1.0039x over previous
#include <cuda_runtime.h>
#include <cuda_bf16.h>
#include <cstdint>

// LogitSeparator: out[b,d,j] = logits[b, start(b,d)+j] for j < len(b,d) else 0
//                 mask[b,d,j] = (j < len) ? 1.0 : 0.0
// start = exclusive cumsum of schemas[b,:] at d; len = schemas[b,d] in [0,256).
// Output layout: [out (B*D*L f32)] ++ [mask (B*D*L f32)]  (verified, rel_err 0).
//
// R13: TMA bulk-store path. Every prior write path converges to ~6 TB/s
// sustained (STG 5.9, pitched CE 5.6, contiguous CE 6.7; no aggregation).
// Untried: cp.async.bulk shared->global. Each CTA stages its full 32KB row
// in SMEM (zeros + live strip) and emits ONE 32KB bulk store — full-line,
// burst-sequential writes like the fill engine. Single launch, no side
// streams (also fixes R12's teardown-memory violation).

#define D_DIM 32
#define VEC_PER_ROW 2048      // L/4 float4 vectors = 32KB

__global__ void __launch_bounds__(128)
bulk_row_kernel(const unsigned int* __restrict__ schemas_w,
                const float* __restrict__ logits,
                float* __restrict__ out,
                int n_rows, int L) {
    __shared__ float4 stage[VEC_PER_ROW];     // 32KB staging = one output row

    const int row  = blockIdx.x;              // b*D + d
    const int half = blockIdx.y;              // 0 = values, 1 = mask
    const int b    = row >> 5;                // D_DIM == 32
    const int d    = row & (D_DIM - 1);
    const int tid  = threadIdx.x;

    // ---- zero the staging row (128 threads x 16 float4) ----
    const float4 z4 = make_float4(0.f, 0.f, 0.f, 0.f);
    #pragma unroll
    for (int i = 0; i < VEC_PER_ROW / 128; i++)
        stage[tid + i * 128] = z4;

    // ---- meta: warps 0-1 redundant scan (lane-indexed, no smem dependency) ----
    int start = 0, len = 0;
    if (tid < 64) {
        const int lane = tid & 31;
        const int idx  = (b << 5) + lane;
        // dtype detect: int64 schemas in [0,256) -> odd 32-bit words all zero
        unsigned int oddw = schemas_w[2 * lane + 1];
        unsigned int v32  = schemas_w[idx];
        bool is64 = (__ballot_sync(0xffffffffu, oddw != 0u) == 0u);
        int v = (int)(is64 ? schemas_w[2 * idx] : v32);

        int x = v;
        #pragma unroll
        for (int o = 1; o < 32; o <<= 1) {
            int y = __shfl_up_sync(0xffffffffu, x, o);
            if (lane >= o) x += y;
        }
        start = __shfl_sync(0xffffffffu, x - v, d);
        len   = __shfl_sync(0xffffffffu, v, d);
    }
    __syncthreads();

    // ---- live strip: vectors 0..63 (len <= 255) ----
    if (tid < 64) {
        const int j = tid << 2;
        float4 w = z4;
        if (half == 0) {
            const float* __restrict__ lrow = logits + (long long)b * L + start;
            if (j + 3 < len) {
                w.x = lrow[j + 0];
                w.y = lrow[j + 1];
                w.z = lrow[j + 2];
                w.w = lrow[j + 3];
            } else if (j < len) {
                if (j + 0 < len) w.x = lrow[j + 0];
                if (j + 1 < len) w.y = lrow[j + 1];
                if (j + 2 < len) w.z = lrow[j + 2];
            }
        } else {
            if (j + 0 < len) w.x = 1.f;
            if (j + 1 < len) w.y = 1.f;
            if (j + 2 < len) w.z = 1.f;
            if (j + 3 < len) w.w = 1.f;
        }
        stage[tid] = w;
    }
    __syncthreads();

    // ---- one 32KB bulk store covers the whole output row ----
    // order generic SMEM writes before the async-proxy read
    asm volatile("fence.proxy.async.shared::cta;" ::: "memory");

    if (tid == 0) {
        float* gdst = out + (half ? (long long)n_rows * L : 0ll)
                          + (long long)row * L;
        uint32_t saddr;
        asm("{ .reg .u64 t; cvta.to.shared.u64 t, %1; cvt.u32.u64 %0, t; }"
            : "=r"(saddr) : "l"(stage));
        asm volatile(
            "cp.async.bulk.global.shared::cta.bulk_group [%0], [%1], %2;"
            :: "l"(gdst), "r"(saddr), "r"((unsigned)(VEC_PER_ROW * 16))
            : "memory");
        asm volatile("cp.async.bulk.commit_group;" ::: "memory");
        asm volatile("cp.async.bulk.wait_group 0;" ::: "memory");
    }
}

extern "C" void kernel_launch(void* const* d_in, const int* in_sizes, int n_in,
                              void* d_out, int out_size) {
    const unsigned int* schemas_w = (const unsigned int*)d_in[0];
    const float*        logits    = (const float*)d_in[1];
    float*              out       = (float*)d_out;

    int n_rows = in_sizes[0];             // B*D = 2048
    int B      = n_rows / D_DIM;          // 64
    int L      = in_sizes[1] / B;         // 8192

    dim3 grid(n_rows, 2);
    bulk_row_kernel<<<grid, 128>>>(schemas_w, logits, out, n_rows, L);
}